// round 3
// baseline (speedup 1.0000x reference)
#include <cuda_runtime.h>
#include <math_constants.h>
#include <cstdint>

#define D_DIM     256
#define M_TILE    64
#define N_TILE    128
#define K_TILE    32
#define XS_STRIDE 68      // 64 rows + 4 pad (float4-aligned, conflict-spread)
#define ES_STRIDE 132     // 128 codes + 4 pad
#define NTHREADS  256
#define MAX_CODES 16384

__device__ float  g_enorm2[MAX_CODES];
__device__ double g_loss_sum;

__global__ void vq_zero() { g_loss_sum = 0.0; }

// ||e||^2 per code, one warp per code (order-free thanks to the lattice-shift argument:
// en ~1e-6 only perturbs the final add at magnitude ~256 near rounding boundaries).
__global__ void vq_enorm(const float* __restrict__ emb, int ncodes) {
    int warp = (blockIdx.x * blockDim.x + threadIdx.x) >> 5;
    int lane = threadIdx.x & 31;
    if (warp >= ncodes) return;
    const float* e = emb + (size_t)warp * D_DIM;
    float s = 0.f;
#pragma unroll
    for (int t = 0; t < D_DIM / 32; ++t) {
        float v = e[lane + t * 32];
        s = __fadd_rn(s, __fmul_rn(v, v));
    }
#pragma unroll
    for (int off = 16; off; off >>= 1)
        s = __fadd_rn(s, __shfl_xor_sync(0xffffffffu, s, off));
    if (lane == 0) g_enorm2[warp] = s;
}

// Fused: fp32 GEMM scores + exact-formula dist + argmin(first-index ties) +
// y = fl(x + fl(q - x)) + loss partial sums.
__global__ void __launch_bounds__(NTHREADS, 1)
vq_main(const float* __restrict__ x, const float* __restrict__ emb,
        float* __restrict__ y_out, float* __restrict__ idx_out,
        int BT, int ncodes)
{
    extern __shared__ float smem[];
    float*  xs = smem;                                  // D_DIM * XS_STRIDE (x tile, transposed)
    float*  es = xs + D_DIM * XS_STRIDE;                // 2 * K_TILE * ES_STRIDE (double buffer)
    float*  xn = es + 2 * K_TILE * ES_STRIDE;           // M_TILE
    float*  bd = xn + M_TILE;                           // M_TILE * 16
    int*    bi = (int*)(bd + M_TILE * 16);              // M_TILE * 16
    double* warp_loss = (double*)(bi + M_TILE * 16);    // NTHREADS/32

    const int tid  = threadIdx.x;
    const int row0 = blockIdx.x * M_TILE;

    // Load x tile transposed: xs[k][r]
    for (int i = tid; i < M_TILE * D_DIM; i += NTHREADS) {
        int r = i >> 8;
        int k = i & (D_DIM - 1);
        int gr = row0 + r;
        xs[k * XS_STRIDE + r] = (gr < BT) ? x[(size_t)gr * D_DIM + k] : 0.f;
    }
    __syncthreads();

    // ||f||^2 per row (order-free, lattice-shift argument)
    if (tid < M_TILE) {
        float s = 0.f;
#pragma unroll 8
        for (int k = 0; k < D_DIM; ++k) {
            float v = xs[k * XS_STRIDE + tid];
            s = __fadd_rn(s, __fmul_rn(v, v));
        }
        xn[tid] = s;
    }
    __syncthreads();

    const int ty = tid >> 4;   // 0..15 (row groups of 4)
    const int tx = tid & 15;   // 0..15 (code groups of 8)
    float axn[4];
#pragma unroll
    for (int i = 0; i < 4; ++i) axn[i] = xn[ty * 4 + i];

    float bestd[4]; int besti[4];
#pragma unroll
    for (int i = 0; i < 4; ++i) { bestd[i] = CUDART_INF_F; besti[i] = 0; }

    // emb staging map: thread -> (code lc in tile, kk-halves lp)
    const int lc = tid >> 1;
    const int lp = (tid & 1) * 16;

    const int n_chunks = ncodes / N_TILE;
    for (int nc = 0; nc < n_chunks; ++nc) {
        const int n0 = nc * N_TILE;
        const float* esrc = emb + (size_t)(n0 + lc) * D_DIM + lp;

        float acc[4][8];
#pragma unroll
        for (int i = 0; i < 4; ++i)
#pragma unroll
            for (int j = 0; j < 8; ++j) acc[i][j] = 0.f;

        // prologue: k-chunk 0 -> buffer 0
        {
            float4 st0 = *(const float4*)(esrc + 0);
            float4 st1 = *(const float4*)(esrc + 4);
            float4 st2 = *(const float4*)(esrc + 8);
            float4 st3 = *(const float4*)(esrc + 12);
            float4 st[4] = {st0, st1, st2, st3};
#pragma unroll
            for (int j = 0; j < 4; ++j) {
                es[(lp + j * 4 + 0) * ES_STRIDE + lc] = st[j].x;
                es[(lp + j * 4 + 1) * ES_STRIDE + lc] = st[j].y;
                es[(lp + j * 4 + 2) * ES_STRIDE + lc] = st[j].z;
                es[(lp + j * 4 + 3) * ES_STRIDE + lc] = st[j].w;
            }
        }
        __syncthreads();

#pragma unroll 1
        for (int kc = 0; kc < D_DIM / K_TILE; ++kc) {
            // prefetch next k-chunk into registers (overlaps with FMA work)
            float4 s0, s1, s2, s3;
            const bool hn = (kc + 1 < D_DIM / K_TILE);
            if (hn) {
                const float* p = esrc + (kc + 1) * K_TILE;
                s0 = *(const float4*)(p + 0);
                s1 = *(const float4*)(p + 4);
                s2 = *(const float4*)(p + 8);
                s3 = *(const float4*)(p + 12);
            }
            const float* ec = es + (kc & 1) * (K_TILE * ES_STRIDE);
            const float* xc = xs + kc * K_TILE * XS_STRIDE;
#pragma unroll 8
            for (int kk = 0; kk < K_TILE; ++kk) {
                float4 a  = *(const float4*)(xc + kk * XS_STRIDE + ty * 4);
                float4 b0 = *(const float4*)(ec + kk * ES_STRIDE + tx * 8);
                float4 b1 = *(const float4*)(ec + kk * ES_STRIDE + tx * 8 + 4);
                float av[4] = {a.x, a.y, a.z, a.w};
                float bv[8] = {b0.x, b0.y, b0.z, b0.w, b1.x, b1.y, b1.z, b1.w};
#pragma unroll
                for (int i = 0; i < 4; ++i)
#pragma unroll
                    for (int j = 0; j < 8; ++j)
                        acc[i][j] = __fmaf_rn(av[i], bv[j], acc[i][j]);
            }
            if (hn) {
                __syncthreads();
                float* dst = es + ((kc + 1) & 1) * (K_TILE * ES_STRIDE);
                float4 st[4] = {s0, s1, s2, s3};
#pragma unroll
                for (int j = 0; j < 4; ++j) {
                    dst[(lp + j * 4 + 0) * ES_STRIDE + lc] = st[j].x;
                    dst[(lp + j * 4 + 1) * ES_STRIDE + lc] = st[j].y;
                    dst[(lp + j * 4 + 2) * ES_STRIDE + lc] = st[j].z;
                    dst[(lp + j * 4 + 3) * ES_STRIDE + lc] = st[j].w;
                }
                __syncthreads();
            }
        }

        // Epilogue: exact reference formula dist = fl(fl(xn - 2*dot) + en).
        // Codes strictly increase per thread -> strict '<' keeps first index.
#pragma unroll
        for (int j = 0; j < 8; ++j) {
            int code = n0 + tx * 8 + j;
            float en = g_enorm2[code];
#pragma unroll
            for (int i = 0; i < 4; ++i) {
                float dist = __fadd_rn(__fsub_rn(axn[i], __fmul_rn(2.0f, acc[i][j])), en);
                if (dist < bestd[i]) { bestd[i] = dist; besti[i] = code; }
            }
        }
    }

    // Cross-thread (tx) argmin per row with (dist, idx) lexicographic tie-break
#pragma unroll
    for (int i = 0; i < 4; ++i) {
        bd[(ty * 4 + i) * 16 + tx] = bestd[i];
        bi[(ty * 4 + i) * 16 + tx] = besti[i];
    }
    __syncthreads();
    if (tid < M_TILE) {
        float d0 = bd[tid * 16]; int i0 = bi[tid * 16];
#pragma unroll
        for (int t = 1; t < 16; ++t) {
            float d = bd[tid * 16 + t]; int ii = bi[tid * 16 + t];
            if (d < d0 || (d == d0 && ii < i0)) { d0 = d; i0 = ii; }
        }
        bi[tid * 16] = i0;
        if (idx_out != nullptr && (row0 + tid) < BT)
            idx_out[row0 + tid] = (float)i0;
    }
    __syncthreads();

    // y = fl(x + fl(q - x)), loss += fl(q-x)^2
    float lsum = 0.f;
    for (int i = tid; i < M_TILE * D_DIM; i += NTHREADS) {
        int r = i >> 8;
        int k = i & (D_DIM - 1);
        int gr = row0 + r;
        if (gr < BT) {
            int code = bi[r * 16];
            float xv = xs[k * XS_STRIDE + r];
            float q  = __ldg(&emb[(size_t)code * D_DIM + k]);
            float df = __fsub_rn(q, xv);
            y_out[(size_t)gr * D_DIM + k] = __fadd_rn(xv, df);
            lsum = __fmaf_rn(df, df, lsum);
        }
    }
#pragma unroll
    for (int off = 16; off; off >>= 1)
        lsum += __shfl_xor_sync(0xffffffffu, lsum, off);
    if ((tid & 31) == 0) warp_loss[tid >> 5] = (double)lsum;
    __syncthreads();
    if (tid == 0) {
        double t = 0.0;
#pragma unroll
        for (int w = 0; w < NTHREADS / 32; ++w) t += warp_loss[w];
        atomicAdd(&g_loss_sum, t);
    }
}

__global__ void vq_finalize(float* __restrict__ loss_out, double inv_n) {
    loss_out[0] = (float)(g_loss_sum * inv_n);
}

extern "C" void kernel_launch(void* const* d_in, const int* in_sizes, int n_in,
                              void* d_out, int out_size)
{
    // x is the big tensor, emb the small one (defensive against ordering)
    int xi = 0, ei = 1;
    if (n_in >= 2 && in_sizes[1] > in_sizes[0]) { xi = 1; ei = 0; }
    const float* x   = (const float*)d_in[xi];
    const float* emb = (const float*)d_in[ei];
    const int BT     = in_sizes[xi] / D_DIM;     // 65536
    const int ncodes = in_sizes[ei] / D_DIM;     // 8192

    float* out = (float*)d_out;
    const long long yN = (long long)BT * D_DIM;
    float* idxp = ((long long)out_size >= yN + BT) ? out + yN : nullptr;
    const bool has_loss = ((long long)out_size >= yN + BT + 1);

    const size_t SMEM =
        (size_t)(D_DIM * XS_STRIDE + 2 * K_TILE * ES_STRIDE + M_TILE + M_TILE * 16) * sizeof(float)
        + (size_t)(M_TILE * 16) * sizeof(int)
        + (NTHREADS / 32) * sizeof(double);
    cudaFuncSetAttribute((const void*)vq_main,
                         cudaFuncAttributeMaxDynamicSharedMemorySize, (int)SMEM);

    vq_zero<<<1, 1>>>();
    vq_enorm<<<(ncodes * 32 + NTHREADS - 1) / NTHREADS, NTHREADS>>>(emb, ncodes);
    const int grid = (BT + M_TILE - 1) / M_TILE;
    vq_main<<<grid, NTHREADS, SMEM>>>(x, emb, out, idxp, BT, ncodes);
    if (has_loss)
        vq_finalize<<<1, 1>>>(out + yN + BT, 1.0 / ((double)BT * (double)D_DIM));
}

// round 5
// speedup vs baseline: 1.0619x; 1.0619x over previous
#include <cuda_runtime.h>
#include <cuda_bf16.h>
#include <math_constants.h>
#include <cstdint>
#include <cstring>

#define D_DIM   256
#define CAP     16
#define MARGIN  3.0e-4f
#define MAXBT   65536
#define MAXCODE 8192

// ---------------- static device scratch (no allocations) ----------------
__device__ float         g_en[MAXCODE];
__device__ double        g_loss;
__device__ __nv_bfloat16 g_embs[(size_t)MAXCODE * D_DIM];   // 4 MB staged bf16
__device__ float         g_cs[(size_t)MAXBT * CAP];
__device__ int           g_ci[(size_t)MAXBT * CAP];
__device__ int           g_cn[MAXBT];

// ---------------- PTX helpers (all baseline sm_80-level features) --------
__device__ __forceinline__ uint32_t smem_u32(const void* p) {
    uint32_t r;
    asm("{ .reg .u64 t; cvta.to.shared.u64 t, %1; cvt.u32.u64 %0, t; }" : "=r"(r) : "l"(p));
    return r;
}
__device__ __forceinline__ void cp16(uint32_t dst, const void* src) {
    asm volatile("cp.async.cg.shared.global [%0], [%1], 16;" :: "r"(dst), "l"(src) : "memory");
}
#define CP_COMMIT() asm volatile("cp.async.commit_group;" ::: "memory")
#define CP_WAIT(n)  asm volatile("cp.async.wait_group %0;" :: "n"(n) : "memory")

#define LDMX4(r0, r1, r2, r3, a) \
    asm volatile("ldmatrix.sync.aligned.m8n8.x4.shared.b16 {%0,%1,%2,%3}, [%4];" \
                 : "=r"(r0), "=r"(r1), "=r"(r2), "=r"(r3) : "r"(a))

#define MMA16816(d, a, b0, b1) \
    asm volatile("mma.sync.aligned.m16n8k16.row.col.f32.bf16.bf16.f32 " \
                 "{%0,%1,%2,%3}, {%4,%5,%6,%7}, {%8,%9}, {%0,%1,%2,%3};" \
                 : "+f"((d)[0]), "+f"((d)[1]), "+f"((d)[2]), "+f"((d)[3]) \
                 : "r"((a)[0]), "r"((a)[1]), "r"((a)[2]), "r"((a)[3]), "r"(b0), "r"(b1))

// ---------------- smem layout for pass1 -----------------------------------
#define MSTR    264                         // halves per row (256 + 8 pad)
#define RSTRB   528                         // bytes per row
#define OFF_AS  0
#define A_SZ    (128 * RSTRB)               // 67584
#define OFF_BS  A_SZ
#define B_SZ    (128 * RSTRB)               // 67584 per buffer
#define OFF_CM  (OFF_BS + 2 * B_SZ)         // 202752
#define OFF_RM  (OFF_CM + 128 * 17 * 4)     // 211456
#define OFF_TH  (OFF_RM + 512)              // 211968
#define SMEM1   (OFF_TH + 512)              // 212480

// ---------------- K0: zero loss + counters --------------------------------
__global__ void vq_zero() {
    int i = blockIdx.x * blockDim.x + threadIdx.x;
    if (i == 0) g_loss = 0.0;
    if (i < MAXBT) g_cn[i] = 0;
}

// ---------------- K1: ||e||^2 (round-1 exact formula) + bf16 staging ------
__global__ void vq_stage(const float* __restrict__ emb, int ncodes) {
    int code = (blockIdx.x * blockDim.x + threadIdx.x) >> 5;
    int lane = threadIdx.x & 31;
    if (code >= ncodes) return;
    const float* e = emb + (size_t)code * D_DIM;
    float s = 0.f;
#pragma unroll
    for (int t = 0; t < 8; ++t) {
        float v = e[lane + t * 32];
        s = __fadd_rn(s, __fmul_rn(v, v));
    }
#pragma unroll
    for (int o = 16; o; o >>= 1) s = __fadd_rn(s, __shfl_xor_sync(0xffffffffu, s, o));
    if (lane == 0) g_en[code] = s;
#pragma unroll
    for (int t = 0; t < 8; ++t) {
        int k = lane + t * 32;
        g_embs[(size_t)code * D_DIM + k] = __float2bfloat16(e[k]);
    }
}

// ---------------- K2: HMMA scoring + exact-threshold candidate collect ----
__global__ void __launch_bounds__(256, 1)
vq_pass1(const float* __restrict__ x, int BT, int ncodes)
{
    extern __shared__ char sm[];
    const uint32_t sb = smem_u32(sm);
    const int tid = threadIdx.x, wid = tid >> 5, lane = tid & 31;
    const int wy = wid >> 2, wx = wid & 3;       // 2x4 warp grid: 64x32 tiles
    const int row0 = blockIdx.x * 128;
    const int NC = ncodes >> 7;
    float* s_cm  = (float*)(sm + OFF_CM);
    float* s_rm  = (float*)(sm + OFF_RM);
    float* s_thr = (float*)(sm + OFF_TH);

    // A = bf16(-2x): 128 rows x 256, padded stride
    for (int p = tid; p < 16384; p += 256) {
        int row = p >> 7, pc = p & 127, gr = row0 + row;
        float2 v = (gr < BT) ? *(const float2*)(x + (size_t)gr * D_DIM + pc * 2)
                             : make_float2(0.f, 0.f);
        __nv_bfloat162 bv = __floats2bfloat162_rn(-2.f * v.x, -2.f * v.y);
        uint32_t w; memcpy(&w, &bv, 4);
        *(uint32_t*)(sm + OFF_AS + row * RSTRB + pc * 4) = w;
    }
    if (tid < 128) s_rm[tid] = CUDART_INF_F;

    // prologue: chunks 0,1 -> buffers 0,1
#pragma unroll
    for (int c = 0; c < 2; ++c) {
        if (c < NC) {
            const char* src = (const char*)(g_embs + (size_t)c * 128 * D_DIM);
#pragma unroll
            for (int i = 0; i < 16; ++i) {
                int t = tid + i * 256, r = t >> 5, q = t & 31;
                cp16(sb + OFF_BS + c * B_SZ + r * RSTRB + q * 16, src + r * 512 + q * 16);
            }
        }
        CP_COMMIT();
    }

    const int lr = lane >> 2, lc2 = (lane & 3) * 2;
    const int stream = wx * 4 + (lane & 3);

    for (int nc = 0; nc < NC; ++nc) {
        const int buf = nc & 1;
        if (nc + 1 < NC) { CP_WAIT(1); } else { CP_WAIT(0); }
        __syncthreads();

        float acc[4][4][4];
#pragma unroll
        for (int mi = 0; mi < 4; ++mi)
#pragma unroll
            for (int ni = 0; ni < 4; ++ni)
#pragma unroll
                for (int c = 0; c < 4; ++c) acc[mi][ni][c] = 0.f;

        const uint32_t Ab = sb + OFF_AS + wy * 64 * RSTRB;
        const uint32_t Bb = sb + OFF_BS + buf * B_SZ + wx * 32 * RSTRB;
        const uint32_t lrow = (uint32_t)(lane & 15) * RSTRB + (uint32_t)(lane >> 4) * 16;

#pragma unroll 1
        for (int ks = 0; ks < 16; ++ks) {
            uint32_t bfr[4][2];
#pragma unroll
            for (int nh = 0; nh < 2; ++nh) {
                uint32_t t0, t1, t2, t3;
                LDMX4(t0, t1, t2, t3, Bb + nh * 16 * RSTRB + lrow + ks * 32);
                bfr[2 * nh][0] = t0; bfr[2 * nh][1] = t2;
                bfr[2 * nh + 1][0] = t1; bfr[2 * nh + 1][1] = t3;
            }
#pragma unroll
            for (int mi = 0; mi < 4; ++mi) {
                uint32_t a[4];
                LDMX4(a[0], a[1], a[2], a[3], Ab + mi * 16 * RSTRB + lrow + ks * 32);
#pragma unroll
                for (int ni = 0; ni < 4; ++ni)
                    MMA16816(acc[mi][ni], a, bfr[ni][0], bfr[ni][1]);
            }
        }

        // exact per-chunk row-min: lane-min over 8 vals/row -> smem streams
#pragma unroll
        for (int mi = 0; mi < 4; ++mi)
#pragma unroll
            for (int h = 0; h < 2; ++h) {
                int rowl = wy * 64 + mi * 16 + lr + 8 * h;
                float v = CUDART_INF_F;
#pragma unroll
                for (int ni = 0; ni < 4; ++ni)
                    v = fminf(v, fminf(acc[mi][ni][2 * h], acc[mi][ni][2 * h + 1]));
                s_cm[rowl * 17 + stream] = v;
            }
        __syncthreads();
        if (tid < 128) {
            float m = s_cm[tid * 17];
#pragma unroll
            for (int s = 1; s < 16; ++s) m = fminf(m, s_cm[tid * 17 + s]);
            float rm = fminf(s_rm[tid], m);
            s_rm[tid] = rm;
            s_thr[tid] = rm + MARGIN;
        }
        __syncthreads();

        // prefetch chunk nc+2 into freed buffer (all reads of buf done)
        if (nc + 2 < NC) {
            const char* src = (const char*)(g_embs + (size_t)(nc + 2) * 128 * D_DIM);
#pragma unroll
            for (int i = 0; i < 16; ++i) {
                int t = tid + i * 256, r = t >> 5, q = t & 31;
                cp16(sb + OFF_BS + buf * B_SZ + r * RSTRB + q * 16, src + r * 512 + q * 16);
            }
            CP_COMMIT();
        }

        // appends: threshold = exact running row min + MARGIN
#pragma unroll
        for (int mi = 0; mi < 4; ++mi)
#pragma unroll
            for (int h = 0; h < 2; ++h) {
                int rowl = wy * 64 + mi * 16 + lr + 8 * h;
                int grow = row0 + rowl;
                float th = s_thr[rowl];
#pragma unroll
                for (int ni = 0; ni < 4; ++ni)
#pragma unroll
                    for (int c = 0; c < 2; ++c) {
                        float v = acc[mi][ni][2 * h + c];
                        if (v <= th && grow < BT) {
                            int code = nc * 128 + wx * 32 + ni * 8 + lc2 + c;
                            int pos = atomicAdd(&g_cn[grow], 1);
                            if (pos < CAP) {
                                g_cs[(size_t)grow * CAP + pos] = v;
                                g_ci[(size_t)grow * CAP + pos] = code;
                            }
                        }
                    }
            }
    }
}

// ---------------- K3: exact fp32 recheck (round-1 arithmetic) + epilogue --
__global__ void __launch_bounds__(256)
vq_pass2(const float* __restrict__ x, const float* __restrict__ emb,
         float* __restrict__ y_out, float* __restrict__ idx_out,
         int BT, int ncodes)
{
    __shared__ float  SX[8][256];
    __shared__ double wl[8];
    const int tid = threadIdx.x, w = tid >> 5, lane = tid & 31;
    const int r = blockIdx.x * 8 + w;
    float lsum = 0.f;

    if (r < BT) {
        {   // stage x row
            float4 a = *(const float4*)(x + (size_t)r * D_DIM + lane * 8);
            float4 b = *(const float4*)(x + (size_t)r * D_DIM + lane * 8 + 4);
            *(float4*)(&SX[w][lane * 8]) = a;
            *(float4*)(&SX[w][lane * 8 + 4]) = b;
        }
        __syncwarp();

        const int cntraw = g_cn[r];
        int winner;

        if (cntraw > CAP) {
            // overflow fallback: full exact scan (round-1 arithmetic per code)
            float x2 = 0.f;
            for (int k = 0; k < D_DIM; ++k) {
                float xv = SX[w][k];
                x2 = __fadd_rn(x2, __fmul_rn(xv, xv));
            }
            float bd = CUDART_INF_F; int bc = 0x7fffffff;
            for (int c = lane; c < ncodes; c += 32) {
                const float* e = emb + (size_t)c * D_DIM;
                float acc = 0.f;
                for (int k = 0; k < D_DIM; ++k)
                    acc = __fmaf_rn(SX[w][k], __ldg(e + k), acc);
                float d = __fadd_rn(__fsub_rn(x2, __fmul_rn(2.0f, acc)), g_en[c]);
                if (d < bd) { bd = d; bc = c; }
            }
#pragma unroll
            for (int o = 16; o; o >>= 1) {
                float od = __shfl_xor_sync(0xffffffffu, bd, o);
                int   oc = __shfl_xor_sync(0xffffffffu, bc, o);
                if (od < bd || (od == bd && oc < bc)) { bd = od; bc = oc; }
            }
            winner = bc;
        } else {
            const int cnt = cntraw;
            float s = (lane < cnt) ? g_cs[(size_t)r * CAP + lane] : CUDART_INF_F;
            int   c = (lane < cnt) ? g_ci[(size_t)r * CAP + lane] : 0x7fffffff;
            float smin = s;
#pragma unroll
            for (int o = 16; o; o >>= 1) smin = fminf(smin, __shfl_xor_sync(0xffffffffu, smin, o));
            const bool surv = s <= smin + MARGIN;
            const int nsurv = __popc(__ballot_sync(0xffffffffu, surv));

            float d = CUDART_INF_F; int cid = 0x7fffffff;
            if (nsurv == 1) {
                if (surv) { d = 0.f; cid = c; }
            } else if (surv) {
                const float* e = emb + (size_t)c * D_DIM;
                float acc = 0.f, x2 = 0.f;
#pragma unroll 8
                for (int k = 0; k < D_DIM; ++k) {
                    float xv = SX[w][k];
                    x2  = __fadd_rn(x2, __fmul_rn(xv, xv));
                    acc = __fmaf_rn(xv, __ldg(e + k), acc);
                }
                d = __fadd_rn(__fsub_rn(x2, __fmul_rn(2.0f, acc)), g_en[c]);
                cid = c;
            }
#pragma unroll
            for (int o = 16; o; o >>= 1) {
                float od = __shfl_xor_sync(0xffffffffu, d, o);
                int   oc = __shfl_xor_sync(0xffffffffu, cid, o);
                if (od < d || (od == d && oc < cid)) { d = od; cid = oc; }
            }
            winner = cid;
        }

        if (lane == 0 && idx_out != nullptr) idx_out[r] = (float)winner;

        const float* q = emb + (size_t)winner * D_DIM;
        float4 qa = *(const float4*)(q + lane * 8);
        float4 qb = *(const float4*)(q + lane * 8 + 4);
        float qv[8], xv[8], yv[8];
        *(float4*)(qv) = qa; *(float4*)(qv + 4) = qb;
        *(float4*)(xv) = *(float4*)(&SX[w][lane * 8]);
        *(float4*)(xv + 4) = *(float4*)(&SX[w][lane * 8 + 4]);
#pragma unroll
        for (int t = 0; t < 8; ++t) {
            float df = __fsub_rn(qv[t], xv[t]);
            yv[t] = __fadd_rn(xv[t], df);
            lsum = __fmaf_rn(df, df, lsum);
        }
        *(float4*)(y_out + (size_t)r * D_DIM + lane * 8) = *(float4*)(yv);
        *(float4*)(y_out + (size_t)r * D_DIM + lane * 8 + 4) = *(float4*)(yv + 4);
    }
#pragma unroll
    for (int o = 16; o; o >>= 1) lsum += __shfl_xor_sync(0xffffffffu, lsum, o);
    if (lane == 0) wl[w] = (double)lsum;
    __syncthreads();
    if (tid == 0) {
        double t = 0.0;
#pragma unroll
        for (int i = 0; i < 8; ++i) t += wl[i];
        atomicAdd(&g_loss, t);
    }
}

__global__ void vq_fin(float* __restrict__ loss_out, double inv_n) {
    loss_out[0] = (float)(g_loss * inv_n);
}

// --------------------------------- launch ---------------------------------
extern "C" void kernel_launch(void* const* d_in, const int* in_sizes, int n_in,
                              void* d_out, int out_size)
{
    int xi = 0, ei = 1;
    if (n_in >= 2 && in_sizes[1] > in_sizes[0]) { xi = 1; ei = 0; }
    const float* x   = (const float*)d_in[xi];
    const float* emb = (const float*)d_in[ei];
    const int BT     = in_sizes[xi] / D_DIM;
    const int ncodes = in_sizes[ei] / D_DIM;

    float* out = (float*)d_out;
    const long long yN = (long long)BT * D_DIM;
    float* idxp = ((long long)out_size >= yN + BT) ? out + yN : nullptr;
    const bool has_loss = ((long long)out_size >= yN + BT + 1);

    cudaFuncSetAttribute((const void*)vq_pass1,
                         cudaFuncAttributeMaxDynamicSharedMemorySize, SMEM1);

    vq_zero<<<256, 256>>>();
    vq_stage<<<(ncodes * 32 + 255) / 256, 256>>>(emb, ncodes);
    vq_pass1<<<(BT + 127) / 128, 256, SMEM1>>>(x, BT, ncodes);
    vq_pass2<<<(BT + 7) / 8, 256>>>(x, emb, out, idxp, BT, ncodes);
    if (has_loss)
        vq_fin<<<1, 1>>>(out + yN + BT, 1.0 / ((double)BT * (double)D_DIM));
}